// round 5
// baseline (speedup 1.0000x reference)
#include <cuda_runtime.h>

#define THREADS 256
#define TT 30
#define RS 68   // row stride (swizzle padding)

typedef unsigned long long ull;

// ---------------- shared memory layout (float offsets) ----------------
#define WT     0        // P1: W1' [80][256]=20480 ; P2: W3' [32][128]=4096
#define W2o    20480    // P1: W2' [96][128]=12288
#define W4o    4096     // P2: W4' [96][256]=24576
#define WOUTo  28672    // P2: Wout' [64][16]=1024
#define WIH3o  29696    // P2: Wih3' [32][128]=4096   (ends 33792)
#define B1o    33792    // 256
#define B2o    34048    // 128
#define B3o    34176    // 128
#define B4o    34304    // 256
#define BOo    34560    // 16
// state [k][row] stride RS, rows swizzled: phys(r) = r + 4*(r>=32)
#define XINo   34576    // 2 x [16][68] = 2176
#define H1o    36752    // 2 x [64][68] = 8704   (P2: h4)
#define H2o    45456    // 2 x [32][68] = 4352   (P2: h3)
#define SHF    49808    // 199232 bytes

__device__ __forceinline__ void ffma2(ull &acc, ull a, ull b){
    asm("fma.rn.f32x2 %0, %1, %2, %0;" : "+l"(acc) : "l"(a), "l"(b));
}
__device__ __forceinline__ ull bcast2(float w){
    ull r; asm("mov.b64 %0, {%1, %1};" : "=l"(r) : "f"(w)); return r;
}
__device__ __forceinline__ ull pack2(float x, float y){
    ull r; asm("mov.b64 %0, {%1, %2};" : "=l"(r) : "f"(x), "f"(y)); return r;
}
__device__ __forceinline__ float2 unpack2(ull v){
    float2 f; asm("mov.b64 {%0, %1}, %2;" : "=f"(f.x), "=f"(f.y) : "l"(v)); return f;
}
__device__ __forceinline__ float ex2x(float x){
    float e; asm("ex2.approx.f32 %0, %1;" : "=f"(e) : "f"(x)); return e;
}
__device__ __forceinline__ float rcpx(float x){
    float r; asm("rcp.approx.f32 %0, %1;" : "=f"(r) : "f"(x)); return r;
}

// 8-MUFU LSTM activation: ei,ef,eg,eo,ec (5 ex2) + 3 rcp (shared denominators).
// gate order i,f,g,o. Returns h, updates c.
__device__ __forceinline__ float act8(float zi, float zf, float zg, float zo, float &c){
    const float K1 = -1.4426950408889634f;       // -log2(e)
    float ei = ex2x(K1 * zi);
    float ef = ex2x(K1 * zf);
    float eg = ex2x(2.0f * K1 * zg);
    float eo = ex2x(K1 * zo);
    float A = 1.0f + ei, F = 1.0f + ef, G = 1.0f + eg, O = 1.0f + eo;
    float it = (1.0f - eg) * rcpx(A * G);        // sig(zi)*tanh(zg)
    float cn = fmaf(c, rcpx(F), it);             // sig(zf)*c + it
    float ec = ex2x(2.0f * K1 * cn);
    float C = 1.0f + ec;
    c = cn;
    return (1.0f - ec) * rcpx(O * C);            // sig(zo)*tanh(cn)
}

// acc[j][g][p] += sum_k W[k][u][g] * in[k][pr0+2p..]
template<int NU, int NG>
__device__ __forceinline__ void accum(const float* __restrict__ in,
                                      const float* __restrict__ W,
                                      int K, ull (&acc)[NU][4][4], int pr0)
{
#pragma unroll 4
    for (int k = 0; k < K; k++) {
        ulonglong2 hA = *reinterpret_cast<const ulonglong2*>(in + k*RS + pr0);
        ulonglong2 hB = *reinterpret_cast<const ulonglong2*>(in + k*RS + pr0 + 4);
        ull hp0 = hA.x, hp1 = hA.y, hp2 = hB.x, hp3 = hB.y;
#pragma unroll
        for (int j = 0; j < NU; j++) {
            float4 w = *reinterpret_cast<const float4*>(W + k*NG + j*4);
            ull w0 = bcast2(w.x), w1 = bcast2(w.y), w2 = bcast2(w.z), w3 = bcast2(w.w);
            ffma2(acc[j][0][0], w0, hp0); ffma2(acc[j][0][1], w0, hp1);
            ffma2(acc[j][0][2], w0, hp2); ffma2(acc[j][0][3], w0, hp3);
            ffma2(acc[j][1][0], w1, hp0); ffma2(acc[j][1][1], w1, hp1);
            ffma2(acc[j][1][2], w1, hp2); ffma2(acc[j][1][3], w1, hp3);
            ffma2(acc[j][2][0], w2, hp0); ffma2(acc[j][2][1], w2, hp1);
            ffma2(acc[j][2][2], w2, hp2); ffma2(acc[j][2][3], w2, hp3);
            ffma2(acc[j][3][0], w3, hp0); ffma2(acc[j][3][1], w3, hp1);
            ffma2(acc[j][3][2], w3, hp2); ffma2(acc[j][3][3], w3, hp3);
        }
    }
}

template<int NU>
__device__ __forceinline__ void init_acc(ull (&acc)[NU][4][4], const ull (&b)[NU][4]){
#pragma unroll
    for (int j = 0; j < NU; j++)
#pragma unroll
        for (int g = 0; g < 4; g++)
#pragma unroll
            for (int p = 0; p < 4; p++) acc[j][g][p] = b[j][g];
}

template<int NU>
__device__ __forceinline__ void act_store(ull (&acc)[NU][4][4], float (&c)[NU][8],
                                          float* hdst, int pr0)
{
#pragma unroll
    for (int j = 0; j < NU; j++)
#pragma unroll
    for (int p = 0; p < 4; p++) {
        float2 zi = unpack2(acc[j][0][p]);
        float2 zf = unpack2(acc[j][1][p]);
        float2 zg = unpack2(acc[j][2][p]);
        float2 zo = unpack2(acc[j][3][p]);
        float h0 = act8(zi.x, zf.x, zg.x, zo.x, c[j][2*p]);
        float h1 = act8(zi.y, zf.y, zg.y, zo.y, c[j][2*p+1]);
        *reinterpret_cast<ull*>(hdst + j*RS + pr0 + 2*p) = pack2(h0, h1);
    }
}

__global__ void __launch_bounds__(THREADS, 1)
lstm_ae(const float* __restrict__ x,
        const float* __restrict__ Wih1, const float* __restrict__ Whh1, const float* __restrict__ b1,
        const float* __restrict__ Wih2, const float* __restrict__ Whh2, const float* __restrict__ b2,
        const float* __restrict__ Wih3, const float* __restrict__ Whh3, const float* __restrict__ b3,
        const float* __restrict__ Wih4, const float* __restrict__ Whh4, const float* __restrict__ b4,
        const float* __restrict__ Wout, const float* __restrict__ bout,
        float* __restrict__ out)
{
    extern __shared__ float sh[];
    const int tid = threadIdx.x;
    const int wid = tid >> 5;
    const bool grpA = ((wid >> 2) & 1) == 0;  // SMSP pairs (w, w+4) differ
    const long row0 = (long)blockIdx.x * 64;

    const int u0a = (tid >> 3) * 2;
    const int u0b = (tid >> 3);
    const int r0  = (tid & 7) * 8;
    const int pr0 = r0 + ((r0 & 32) >> 3);

    // ---- phase-1 weights (interleaved [k][u][g]) + biases ----
    for (int i = tid; i < 20480; i += THREADS) {
        int k = i >> 8, j = i & 255, u = j >> 2, g = j & 3, row = g * 64 + u;
        sh[WT + i] = (k < 16) ? Wih1[row * 16 + k] : Whh1[row * 64 + (k - 16)];
    }
    for (int i = tid; i < 12288; i += THREADS) {
        int k = i >> 7, j = i & 127, u = j >> 2, g = j & 3, row = g * 32 + u;
        sh[W2o + i] = (k < 64) ? Wih2[row * 64 + k] : Whh2[row * 32 + (k - 64)];
    }
    if (tid < 256) { int u = tid >> 2, g = tid & 3; sh[B1o + tid] = b1[g * 64 + u]; }
    if (tid < 128) { int u = tid >> 2, g = tid & 3; sh[B2o + tid] = b2[g * 32 + u]; }
    if (tid < 128) { int u = tid >> 2, g = tid & 3; sh[B3o + tid] = b3[g * 32 + u]; }
    if (tid < 256) { int u = tid >> 2, g = tid & 3; sh[B4o + tid] = b4[g * 64 + u]; }
    if (tid < 16)  sh[BOo + tid] = bout[tid];
    for (int i = tid; i < 4352; i += THREADS) sh[H1o + i] = 0.f;
    for (int i = tid; i < 2176; i += THREADS) sh[H2o + i] = 0.f;
    {
        int f0 = (tid & 3) * 4, r = tid >> 2;
        int pr = r + ((r & 32) >> 3);
        float4 gx = *reinterpret_cast<const float4*>(x + (row0 + r) * (TT * 16) + f0);
        sh[XINo + (f0 + 0) * RS + pr] = gx.x;
        sh[XINo + (f0 + 1) * RS + pr] = gx.y;
        sh[XINo + (f0 + 2) * RS + pr] = gx.z;
        sh[XINo + (f0 + 3) * RS + pr] = gx.w;
    }
    __syncthreads();

    ull b1p[2][4], b2p[1][4];
#pragma unroll
    for (int j = 0; j < 2; j++)
#pragma unroll
        for (int g = 0; g < 4; g++) b1p[j][g] = bcast2(sh[B1o + (u0a + j) * 4 + g]);
#pragma unroll
    for (int g = 0; g < 4; g++) b2p[0][g] = bcast2(sh[B2o + u0b * 4 + g]);

    float c1[2][8], c2[1][8];
#pragma unroll
    for (int j = 0; j < 2; j++)
#pragma unroll
        for (int q = 0; q < 8; q++) c1[j][q] = 0.f;
#pragma unroll
    for (int q = 0; q < 8; q++) c2[0][q] = 0.f;

    // ---- phase 1: encoder. accL1 enters each t as b1 + Whh1@h1(t-1). ----
    ull accL1[2][4][4], accL2[1][4][4];
    init_acc<2>(accL1, b1p);                 // h1(-1) = 0

    for (int t = 0; t < TT; t++) {
        const int p = t & 1;
        // S1: finish z1 with x-part; actL1 || L2hh-gemm (staggered)
        float4 gx;
        const bool pf = (t + 1 < TT);
        if (pf) gx = *reinterpret_cast<const float4*>(
            x + (row0 + (tid >> 2)) * (TT * 16) + (t + 1) * 16 + (tid & 3) * 4);
        accum<2, 256>(sh + XINo + p * (16 * RS), sh + WT + u0a * 4, 16, accL1, pr0);
        if (pf) {
            int f0 = (tid & 3) * 4, r = tid >> 2;
            int pr = r + ((r & 32) >> 3);
            float* xb = sh + XINo + (p ^ 1) * (16 * RS);
            xb[(f0 + 0) * RS + pr] = gx.x;
            xb[(f0 + 1) * RS + pr] = gx.y;
            xb[(f0 + 2) * RS + pr] = gx.z;
            xb[(f0 + 3) * RS + pr] = gx.w;
        }
        if (grpA) {
            act_store<2>(accL1, c1, sh + H1o + (p ^ 1) * (64 * RS) + u0a * RS, pr0);
            init_acc<1>(accL2, b2p);
            accum<1, 128>(sh + H2o + p * (32 * RS), sh + W2o + 64 * 128 + u0b * 4, 32, accL2, pr0);
        } else {
            init_acc<1>(accL2, b2p);
            accum<1, 128>(sh + H2o + p * (32 * RS), sh + W2o + 64 * 128 + u0b * 4, 32, accL2, pr0);
            act_store<2>(accL1, c1, sh + H1o + (p ^ 1) * (64 * RS) + u0a * RS, pr0);
        }
        __syncthreads();
        // S2: finish z2 with ih-part; actL2 || L1hh-gemm(t+1) (staggered)
        accum<1, 128>(sh + H1o + (p ^ 1) * (64 * RS), sh + W2o + u0b * 4, 64, accL2, pr0);
        if (grpA) {
            act_store<1>(accL2, c2, sh + H2o + (p ^ 1) * (32 * RS) + u0b * RS, pr0);
            init_acc<2>(accL1, b1p);
            accum<2, 256>(sh + H1o + (p ^ 1) * (64 * RS), sh + WT + 16 * 256 + u0a * 4, 64, accL1, pr0);
        } else {
            init_acc<2>(accL1, b1p);
            accum<2, 256>(sh + H1o + (p ^ 1) * (64 * RS), sh + WT + 16 * 256 + u0a * 4, 64, accL1, pr0);
            act_store<1>(accL2, c2, sh + H2o + (p ^ 1) * (32 * RS) + u0b * RS, pr0);
        }
        __syncthreads();
    }
    // latent = h2(29) in H2 buf 0

    // ---- phase-2 weights ----
    for (int i = tid; i < 4096; i += THREADS) {
        int k = i >> 7, j = i & 127, u = j >> 2, g = j & 3, row = g * 32 + u;
        sh[WT + i] = Whh3[row * 32 + k];
    }
    for (int i = tid; i < 24576; i += THREADS) {
        int k = i >> 8, j = i & 255, u = j >> 2, g = j & 3, row = g * 64 + u;
        sh[W4o + i] = (k < 32) ? Wih4[row * 32 + k] : Whh4[row * 64 + (k - 32)];
    }
    for (int i = tid; i < 1024; i += THREADS) {
        int jr = i >> 4, f = i & 15;
        sh[WOUTo + i] = Wout[f * 64 + jr];
    }
    for (int i = tid; i < 4096; i += THREADS) {
        int k = i >> 7, j = i & 127, u = j >> 2, g = j & 3, row = g * 32 + u;
        sh[WIH3o + i] = Wih3[row * 32 + k];
    }
    __syncthreads();

    // zin3 = Wih3 @ latent + b3 (constant over t), in registers
    ull zin3[1][4][4];
    {
        ull b3p[1][4];
#pragma unroll
        for (int g = 0; g < 4; g++) b3p[0][g] = bcast2(sh[B3o + u0b * 4 + g]);
        init_acc<1>(zin3, b3p);
        accum<1, 128>(sh + H2o, sh + WIH3o + u0b * 4, 32, zin3, pr0);
        __syncthreads();
        for (int i = tid; i < 2176; i += THREADS) sh[H2o + i] = 0.f;  // h3 buf0
        for (int i = tid; i < 4352; i += THREADS) sh[H1o + i] = 0.f;  // h4 buf0
    }
    __syncthreads();

    ull b4p[2][4];
#pragma unroll
    for (int j = 0; j < 2; j++)
#pragma unroll
        for (int g = 0; g < 4; g++) b4p[j][g] = bcast2(sh[B4o + (u0a + j) * 4 + g]);
    const float boutf = sh[BOo + (tid & 15)];
    const int fo = tid & 15, rb = tid >> 4;
    const int prb = rb * 4 + ((rb & 8) >> 1);

    float c3[1][8], c4[2][8];
#pragma unroll
    for (int q = 0; q < 8; q++) c3[0][q] = 0.f;
#pragma unroll
    for (int j = 0; j < 2; j++)
#pragma unroll
        for (int q = 0; q < 8; q++) c4[j][q] = 0.f;

    // ---- phase 2: decoder. accL3 enters each t as zin3 + Whh3@h3(t-1). ----
    ull accL3[1][4][4], accL4[2][4][4];
#pragma unroll
    for (int g = 0; g < 4; g++)
#pragma unroll
        for (int pp = 0; pp < 4; pp++) accL3[0][g][pp] = zin3[0][g][pp];  // h3(-1)=0

    for (int t = 0; t < TT; t++) {
        const int p = t & 1;
        // S1': actL3 || L4hh-gemm + proj(t-1) (staggered)
        if (grpA) {
            act_store<1>(accL3, c3, sh + H2o + (p ^ 1) * (32 * RS) + u0b * RS, pr0);
            init_acc<2>(accL4, b4p);
            accum<2, 256>(sh + H1o + p * (64 * RS), sh + W4o + 32 * 256 + u0a * 4, 64, accL4, pr0);
        } else {
            init_acc<2>(accL4, b4p);
            accum<2, 256>(sh + H1o + p * (64 * RS), sh + W4o + 32 * 256 + u0a * 4, 64, accL4, pr0);
        }
        if (t > 0) {   // projection of h4(t-1), overlapped
            const float* h4 = sh + H1o + p * (64 * RS);
            ull a0 = bcast2(boutf), a1 = a0;
#pragma unroll 8
            for (int j = 0; j < 64; j++) {
                ull w = bcast2(sh[WOUTo + j * 16 + fo]);
                ull hq0 = *reinterpret_cast<const ull*>(h4 + j * RS + prb);
                ull hq1 = *reinterpret_cast<const ull*>(h4 + j * RS + prb + 2);
                ffma2(a0, w, hq0);
                ffma2(a1, w, hq1);
            }
            float2 y01 = unpack2(a0), y23 = unpack2(a1);
            long ob = (row0 + rb * 4) * (TT * 16) + (t - 1) * 16 + fo;
            out[ob]               = y01.x;
            out[ob + TT * 16]     = y01.y;
            out[ob + 2 * TT * 16] = y23.x;
            out[ob + 3 * TT * 16] = y23.y;
        }
        if (!grpA)
            act_store<1>(accL3, c3, sh + H2o + (p ^ 1) * (32 * RS) + u0b * RS, pr0);
        __syncthreads();
        // S2': finish z4 with ih-part; actL4 || L3hh-gemm(t+1) (staggered)
        accum<2, 256>(sh + H2o + (p ^ 1) * (32 * RS), sh + W4o + u0a * 4, 32, accL4, pr0);
        if (grpA) {
            act_store<2>(accL4, c4, sh + H1o + (p ^ 1) * (64 * RS) + u0a * RS, pr0);
#pragma unroll
            for (int g = 0; g < 4; g++)
#pragma unroll
                for (int pp = 0; pp < 4; pp++) accL3[0][g][pp] = zin3[0][g][pp];
            accum<1, 128>(sh + H2o + (p ^ 1) * (32 * RS), sh + WT + u0b * 4, 32, accL3, pr0);
        } else {
#pragma unroll
            for (int g = 0; g < 4; g++)
#pragma unroll
                for (int pp = 0; pp < 4; pp++) accL3[0][g][pp] = zin3[0][g][pp];
            accum<1, 128>(sh + H2o + (p ^ 1) * (32 * RS), sh + WT + u0b * 4, 32, accL3, pr0);
            act_store<2>(accL4, c4, sh + H1o + (p ^ 1) * (64 * RS) + u0a * RS, pr0);
        }
        __syncthreads();
    }
    // final projection: h4(29) in H1 buf 0
    {
        const float* h4 = sh + H1o;
        ull a0 = bcast2(boutf), a1 = a0;
#pragma unroll 8
        for (int j = 0; j < 64; j++) {
            ull w = bcast2(sh[WOUTo + j * 16 + fo]);
            ull hq0 = *reinterpret_cast<const ull*>(h4 + j * RS + prb);
            ull hq1 = *reinterpret_cast<const ull*>(h4 + j * RS + prb + 2);
            ffma2(a0, w, hq0);
            ffma2(a1, w, hq1);
        }
        float2 y01 = unpack2(a0), y23 = unpack2(a1);
        long ob = (row0 + rb * 4) * (TT * 16) + (TT - 1) * 16 + fo;
        out[ob]               = y01.x;
        out[ob + TT * 16]     = y01.y;
        out[ob + 2 * TT * 16] = y23.x;
        out[ob + 3 * TT * 16] = y23.y;
    }
}

extern "C" void kernel_launch(void* const* d_in, const int* in_sizes, int n_in,
                              void* d_out, int out_size)
{
    const float* x    = (const float*)d_in[0];
    const float* Wih1 = (const float*)d_in[1];
    const float* Whh1 = (const float*)d_in[2];
    const float* b1   = (const float*)d_in[3];
    const float* Wih2 = (const float*)d_in[4];
    const float* Whh2 = (const float*)d_in[5];
    const float* b2   = (const float*)d_in[6];
    const float* Wih3 = (const float*)d_in[7];
    const float* Whh3 = (const float*)d_in[8];
    const float* b3   = (const float*)d_in[9];
    const float* Wih4 = (const float*)d_in[10];
    const float* Whh4 = (const float*)d_in[11];
    const float* b4   = (const float*)d_in[12];
    const float* Wout = (const float*)d_in[13];
    const float* bout = (const float*)d_in[14];
    float* out = (float*)d_out;

    cudaFuncSetAttribute(lstm_ae, cudaFuncAttributeMaxDynamicSharedMemorySize,
                         SHF * (int)sizeof(float));
    lstm_ae<<<128, THREADS, SHF * sizeof(float)>>>(
        x, Wih1, Whh1, b1, Wih2, Whh2, b2, Wih3, Whh3, b3,
        Wih4, Whh4, b4, Wout, bout, out);
}